// round 2
// baseline (speedup 1.0000x reference)
#include <cuda_runtime.h>
#include <cstdint>

#define H   50
#define G4  200     // 4*H gate rows per layer
#define E   4       // batch elements per block
#define BSZ 512     // batch size (fixed for this problem instance)
#define NTHREADS 256
#define NPAIR 26    // f32x2 pairs per dot (50 padded to 52)
#define NVEC  13    // ulonglong2 (16B) chunks per h vector

// ---- packed f32x2 FMA (FFMA2) ----
__device__ __forceinline__ void fma2(unsigned long long &d, unsigned long long a, unsigned long long b) {
    asm("fma.rn.f32x2 %0, %1, %2, %0;" : "+l"(d) : "l"(a), "l"(b));
}
__device__ __forceinline__ float hsum2(unsigned long long a) {
    float lo = __uint_as_float((unsigned)(a & 0xffffffffu));
    float hi = __uint_as_float((unsigned)(a >> 32));
    return lo + hi;
}
__device__ __forceinline__ unsigned long long pk2(float lo, float hi) {
    return ((unsigned long long)__float_as_uint(hi) << 32) | (unsigned long long)__float_as_uint(lo);
}
// sigmoid: 1/(1+e^-v); safe at extremes (rcp(inf)=0)
__device__ __forceinline__ float sigf(float v) {
    return __fdividef(1.0f, 1.0f + __expf(-v));
}
// tanh: 1 - 2/(1+e^{2v}); safe at both extremes (no inf/inf)
__device__ __forceinline__ float tanhf_(float v) {
    return 1.0f - __fdividef(2.0f, 1.0f + __expf(2.0f * v));
}

__global__ void __launch_bounds__(NTHREADS, 1) sinelstm_kernel(
    const float* __restrict__ x,
    const float* __restrict__ W_ih1, const float* __restrict__ W_hh1,
    const float* __restrict__ b_ih1, const float* __restrict__ b_hh1,
    const float* __restrict__ W_ih2, const float* __restrict__ W_hh2,
    const float* __restrict__ b_ih2, const float* __restrict__ b_hh2,
    const float* __restrict__ W_lin, const float* __restrict__ b_lin,
    float* __restrict__ out, int T, int TP)
{
    __shared__ __align__(16) float h1s[E][52];   // padded to 52 (pad = 0)
    __shared__ __align__(16) float h2s[E][52];
    __shared__ float gbuf[E][G4];                // reused for layer-1 and layer-2 gates
    __shared__ float part[8];                    // per-warp output partials
    __shared__ float outs_s[E];                  // last output (predict feedback)

    const int t    = threadIdx.x;
    const int base = blockIdx.x * E;

    // -------- load weights into registers (thread t owns gate row t) --------
    unsigned long long w1p[NPAIR], w2a[NPAIR], w2b[NPAIR];
    float bias1 = 0.f, bias2 = 0.f, wx1 = 0.f;
    if (t < G4) {
        #pragma unroll
        for (int p = 0; p < NPAIR; p++) {
            int k = 2 * p;
            float a0 = (k     < H) ? W_hh1[t * H + k]     : 0.f;
            float a1 = (k + 1 < H) ? W_hh1[t * H + k + 1] : 0.f;
            w1p[p] = pk2(a0, a1);
            float c0 = (k     < H) ? W_ih2[t * H + k]     : 0.f;
            float c1v= (k + 1 < H) ? W_ih2[t * H + k + 1] : 0.f;
            w2a[p] = pk2(c0, c1v);
            float d0 = (k     < H) ? W_hh2[t * H + k]     : 0.f;
            float d1 = (k + 1 < H) ? W_hh2[t * H + k + 1] : 0.f;
            w2b[p] = pk2(d0, d1);
        }
        bias1 = b_ih1[t] + b_hh1[t];
        bias2 = b_ih2[t] + b_hh2[t];
        wx1   = W_ih1[t];     // W_ih1 is [4H, 1]
    }

    // -------- update-role mapping: element e = t>>6, unit j = t&63 (j<50 active) --------
    const int ue = t >> 6;
    const int uj = t & 63;
    float c1 = 0.f, c2 = 0.f;                    // cell states live in registers
    const float wlin = (uj < H) ? W_lin[uj] : 0.f;
    const float blin = b_lin[0];

    // zero h state (incl. padding)
    if (t < E * 52) { ((float*)h1s)[t] = 0.f; ((float*)h2s)[t] = 0.f; }
    __syncthreads();

    for (int step = 0; step < TP; ++step) {
        // ---- phase 1: layer-1 gates (uses h1 old) ----
        if (t < G4) {
            #pragma unroll
            for (int e = 0; e < E; e++) {
                float xv = (step < T) ? __ldg(&x[(size_t)(base + e) * T + step]) : outs_s[e];
                const ulonglong2* hv = (const ulonglong2*)h1s[e];
                unsigned long long a0 = 0ull, a1 = 0ull;
                #pragma unroll
                for (int q = 0; q < NVEC; q++) {
                    ulonglong2 h = hv[q];
                    fma2(a0, w1p[2 * q],     h.x);
                    fma2(a1, w1p[2 * q + 1], h.y);
                }
                gbuf[e][t] = hsum2(a0) + hsum2(a1) + bias1 + wx1 * xv;
            }
        }
        __syncthreads();   // A

        // ---- phase 2: layer-1 cell/hidden update ----
        if (uj < H) {
            float gi = gbuf[ue][uj];
            float gf = gbuf[ue][H + uj];
            float gg = gbuf[ue][2 * H + uj];
            float go = gbuf[ue][3 * H + uj];
            c1 = sigf(gf) * c1 + sigf(gi) * tanhf_(gg);
            h1s[ue][uj] = sigf(go) * tanhf_(c1);
        }
        __syncthreads();   // B

        // ---- phase 3: layer-2 gates (uses h1 new + h2 old) ----
        if (t < G4) {
            #pragma unroll
            for (int e = 0; e < E; e++) {
                const ulonglong2* h1v = (const ulonglong2*)h1s[e];
                const ulonglong2* h2v = (const ulonglong2*)h2s[e];
                unsigned long long a0 = 0ull, a1 = 0ull, b0 = 0ull, b1 = 0ull;
                #pragma unroll
                for (int q = 0; q < NVEC; q++) {
                    ulonglong2 ha = h1v[q];
                    ulonglong2 hb = h2v[q];
                    fma2(a0, w2a[2 * q],     ha.x);
                    fma2(a1, w2a[2 * q + 1], ha.y);
                    fma2(b0, w2b[2 * q],     hb.x);
                    fma2(b1, w2b[2 * q + 1], hb.y);
                }
                gbuf[e][t] = hsum2(a0) + hsum2(a1) + hsum2(b0) + hsum2(b1) + bias2;
            }
        }
        __syncthreads();   // C

        // ---- phase 4: layer-2 update + output term + warp reduce ----
        float term = 0.f;
        if (uj < H) {
            float gi = gbuf[ue][uj];
            float gf = gbuf[ue][H + uj];
            float gg = gbuf[ue][2 * H + uj];
            float go = gbuf[ue][3 * H + uj];
            c2 = sigf(gf) * c2 + sigf(gi) * tanhf_(gg);
            float h2 = sigf(go) * tanhf_(c2);
            h2s[ue][uj] = h2;
            term = wlin * h2;
        }
        #pragma unroll
        for (int off = 16; off; off >>= 1)
            term += __shfl_xor_sync(0xffffffffu, term, off);
        if ((t & 31) == 0) part[t >> 5] = term;   // 2 warps per element
        __syncthreads();   // D

        // ---- phase 5: finalize + store output ----
        if (t < E) {
            float o = part[2 * t] + part[2 * t + 1] + blin;
            outs_s[t] = o;
            out[(size_t)(base + t) * TP + step] = o;
        }
        // outs_s only feeds back once step+1 >= T
        if (step >= T - 1) __syncthreads();   // E (predict-phase feedback barrier)
    }
}

extern "C" void kernel_launch(void* const* d_in, const int* in_sizes, int n_in,
                              void* d_out, int out_size) {
    const float* x     = (const float*)d_in[0];
    const float* W_ih1 = (const float*)d_in[1];
    const float* W_hh1 = (const float*)d_in[2];
    const float* b_ih1 = (const float*)d_in[3];
    const float* b_hh1 = (const float*)d_in[4];
    const float* W_ih2 = (const float*)d_in[5];
    const float* W_hh2 = (const float*)d_in[6];
    const float* b_ih2 = (const float*)d_in[7];
    const float* b_hh2 = (const float*)d_in[8];
    const float* W_lin = (const float*)d_in[9];
    const float* b_lin = (const float*)d_in[10];
    // d_in[11] = predict (derived from out_size instead)

    int T  = in_sizes[0] / BSZ;      // 1024
    int TP = out_size   / BSZ;       // 1056 = T + predict

    sinelstm_kernel<<<BSZ / E, NTHREADS>>>(
        x, W_ih1, W_hh1, b_ih1, b_hh1,
        W_ih2, W_hh2, b_ih2, b_hh2,
        W_lin, b_lin, (float*)d_out, T, TP);
}

// round 5
// speedup vs baseline: 1.0126x; 1.0126x over previous
#include <cuda_runtime.h>
#include <cstdint>

#define H    50
#define G4   200     // 4*H gate rows per layer
#define E    4       // batch elements per block
#define BSZ  512
#define NTH  448     // 400 pair-threads (200 rows x 2 K-halves) + update threads
#define NCH  7       // ulonglong2 (16B) chunks per K-half
#define HPAD 56      // h padded to 14 chunks * 4 floats

// ---- packed f32x2 ops ----
__device__ __forceinline__ void fma2(unsigned long long &d, unsigned long long a, unsigned long long b) {
    asm("fma.rn.f32x2 %0, %1, %2, %0;" : "+l"(d) : "l"(a), "l"(b));
}
__device__ __forceinline__ float hsum2(unsigned long long a) {
    return __uint_as_float((unsigned)(a & 0xffffffffu)) + __uint_as_float((unsigned)(a >> 32));
}
__device__ __forceinline__ unsigned long long pk2(float lo, float hi) {
    return ((unsigned long long)__float_as_uint(hi) << 32) | (unsigned long long)__float_as_uint(lo);
}
__device__ __forceinline__ float sigf(float v) {
    return __fdividef(1.0f, 1.0f + __expf(-v));
}
__device__ __forceinline__ float tanhf_(float v) {
    return 1.0f - __fdividef(2.0f, 1.0f + __expf(2.0f * v));
}

__global__ void __launch_bounds__(NTH, 1) sinelstm_kernel(
    const float* __restrict__ x,
    const float* __restrict__ W_ih1, const float* __restrict__ W_hh1,
    const float* __restrict__ b_ih1, const float* __restrict__ b_hh1,
    const float* __restrict__ W_ih2, const float* __restrict__ W_hh2,
    const float* __restrict__ b_ih2, const float* __restrict__ b_hh2,
    const float* __restrict__ W_lin, const float* __restrict__ b_lin,
    float* __restrict__ out, int T, int TP)
{
    __shared__ __align__(16) float h1s[E][HPAD];
    __shared__ __align__(16) float h2s[E][HPAD];
    __shared__ float gbuf1[E][G4];
    __shared__ float gbuf2[E][G4];
    __shared__ float part[8];
    __shared__ float outs_s[E];

    const int t    = threadIdx.x;
    const int base = blockIdx.x * E;
    const int pr   = t >> 1;        // gate row (0..223; rows >=200 are padding)
    const int hf   = t & 1;         // K-half

    // -------- register-resident weights: row pr, K-half hf --------
    unsigned long long w1p[2 * NCH], w2a[2 * NCH], w2b[2 * NCH];
    float bias1 = 0.f, bias2 = 0.f, wx1 = 0.f;
    {
        const bool row_ok = (pr < G4);
        #pragma unroll
        for (int p = 0; p < 2 * NCH; p++) {
            int k = 2 * (hf * 2 * NCH + p);
            float a0 = (row_ok && k     < H) ? W_hh1[pr * H + k]     : 0.f;
            float a1 = (row_ok && k + 1 < H) ? W_hh1[pr * H + k + 1] : 0.f;
            w1p[p] = pk2(a0, a1);
            float c0 = (row_ok && k     < H) ? W_ih2[pr * H + k]     : 0.f;
            float c1v= (row_ok && k + 1 < H) ? W_ih2[pr * H + k + 1] : 0.f;
            w2a[p] = pk2(c0, c1v);
            float d0 = (row_ok && k     < H) ? W_hh2[pr * H + k]     : 0.f;
            float d1 = (row_ok && k + 1 < H) ? W_hh2[pr * H + k + 1] : 0.f;
            w2b[p] = pk2(d0, d1);
        }
        if (row_ok) {
            bias1 = b_ih1[pr] + b_hh1[pr];
            bias2 = b_ih2[pr] + b_hh2[pr];
            wx1   = W_ih1[pr];
        }
    }

    // -------- update role: threads 192..447 (warps 6..13, full warps) --------
    const int  r   = t - 192;
    const int  ue  = (r >> 6) & 3;
    const int  uj  = r & 63;
    const bool urole = (t >= 192);
    const bool upd   = urole && (uj < H);
    float c1 = 0.f, c2 = 0.f;
    const float wlin = upd ? W_lin[uj] : 0.f;
    const float blin = b_lin[0];

    if (t < E * HPAD) { ((float*)h1s)[t] = 0.f; ((float*)h2s)[t] = 0.f; }
    __syncthreads();

    // ================= main loop: 3 barriers/step, lagged h2/out =================
    for (int step = 0; step < T; ++step) {
        // ---- R1: gates1(step) [FMA]  ||  h2/c2 update for step-1 [MUFU] ----
        unsigned long long g1acc[E];
        #pragma unroll
        for (int e = 0; e < E; e++) {
            const ulonglong2* hv = (const ulonglong2*)(&h1s[e][hf * 4 * NCH]);
            unsigned long long acc = 0ull;
            #pragma unroll
            for (int q = 0; q < NCH; q++) {
                ulonglong2 hc = hv[q];
                fma2(acc, w1p[2 * q],     hc.x);
                fma2(acc, w1p[2 * q + 1], hc.y);
            }
            g1acc[e] = acc;
        }
        if (urole) {
            float term = 0.f;
            if (step > 0 && uj < H) {
                float gi = gbuf2[ue][uj];
                float gf = gbuf2[ue][H + uj];
                float gg = gbuf2[ue][2 * H + uj];
                float go = gbuf2[ue][3 * H + uj];
                c2 = sigf(gf) * c2 + sigf(gi) * tanhf_(gg);
                float h2 = sigf(go) * tanhf_(c2);
                h2s[ue][uj] = h2;
                term = wlin * h2;
            }
            #pragma unroll
            for (int off = 16; off; off >>= 1)
                term += __shfl_xor_sync(0xffffffffu, term, off);
            if ((t & 31) == 0) part[(t >> 5) - 6] = term;
        }
        #pragma unroll
        for (int e = 0; e < E; e++) {
            float s = hsum2(g1acc[e]);
            s += __shfl_xor_sync(0xffffffffu, s, 1);      // combine K-halves
            if (hf == 0 && pr < G4) {
                float xv = __ldg(&x[(size_t)(base + e) * T + step]);
                gbuf1[e][pr] = s + bias1 + wx1 * xv;
            }
        }
        __syncthreads();   // A

        if (step > 0 && urole && r < E)
            out[(size_t)(base + r) * TP + (step - 1)] = part[2 * r] + part[2 * r + 1] + blin;

        // ---- R2: W_hh2·h2 partial [FMA, all]  ||  h1/c1 update [MUFU] ----
        unsigned long long g2acc[E];
        #pragma unroll
        for (int e = 0; e < E; e++) {
            const ulonglong2* hv = (const ulonglong2*)(&h2s[e][hf * 4 * NCH]);
            unsigned long long acc = 0ull;
            #pragma unroll
            for (int q = 0; q < NCH; q++) {
                ulonglong2 hc = hv[q];
                fma2(acc, w2b[2 * q],     hc.x);
                fma2(acc, w2b[2 * q + 1], hc.y);
            }
            g2acc[e] = acc;
        }
        if (upd) {
            float gi = gbuf1[ue][uj];
            float gf = gbuf1[ue][H + uj];
            float gg = gbuf1[ue][2 * H + uj];
            float go = gbuf1[ue][3 * H + uj];
            c1 = sigf(gf) * c1 + sigf(gi) * tanhf_(gg);
            h1s[ue][uj] = sigf(go) * tanhf_(c1);
        }
        __syncthreads();   // B

        // ---- R3: + W_ih2·h1(new) → gates2 ----
        #pragma unroll
        for (int e = 0; e < E; e++) {
            const ulonglong2* hv = (const ulonglong2*)(&h1s[e][hf * 4 * NCH]);
            unsigned long long acc = g2acc[e];
            #pragma unroll
            for (int q = 0; q < NCH; q++) {
                ulonglong2 hc = hv[q];
                fma2(acc, w2a[2 * q],     hc.x);
                fma2(acc, w2a[2 * q + 1], hc.y);
            }
            float s = hsum2(acc);
            s += __shfl_xor_sync(0xffffffffu, s, 1);
            if (hf == 0 && pr < G4) gbuf2[e][pr] = s + bias2;
        }
        __syncthreads();   // C
    }

    // ---- epilogue: h2/out for step T-1, seed predict feedback ----
    {
        float term = 0.f;
        if (upd) {
            float gi = gbuf2[ue][uj];
            float gf = gbuf2[ue][H + uj];
            float gg = gbuf2[ue][2 * H + uj];
            float go = gbuf2[ue][3 * H + uj];
            c2 = sigf(gf) * c2 + sigf(gi) * tanhf_(gg);
            float h2 = sigf(go) * tanhf_(c2);
            h2s[ue][uj] = h2;
            term = wlin * h2;
        }
        if (urole) {
            #pragma unroll
            for (int off = 16; off; off >>= 1)
                term += __shfl_xor_sync(0xffffffffu, term, off);
            if ((t & 31) == 0) part[(t >> 5) - 6] = term;
        }
        __syncthreads();
        if (urole && r < E) {
            float o = part[2 * r] + part[2 * r + 1] + blin;
            outs_s[r] = o;
            out[(size_t)(base + r) * TP + (T - 1)] = o;
        }
        __syncthreads();
    }

    // ================= predict loop: strict ordering (output feedback) =================
    for (int step = T; step < TP; ++step) {
        #pragma unroll
        for (int e = 0; e < E; e++) {
            const ulonglong2* hv = (const ulonglong2*)(&h1s[e][hf * 4 * NCH]);
            unsigned long long acc = 0ull;
            #pragma unroll
            for (int q = 0; q < NCH; q++) {
                ulonglong2 hc = hv[q];
                fma2(acc, w1p[2 * q],     hc.x);
                fma2(acc, w1p[2 * q + 1], hc.y);
            }
            float s = hsum2(acc);
            s += __shfl_xor_sync(0xffffffffu, s, 1);
            if (hf == 0 && pr < G4)
                gbuf1[e][pr] = s + bias1 + wx1 * outs_s[e];
        }
        __syncthreads();

        if (upd) {
            float gi = gbuf1[ue][uj];
            float gf = gbuf1[ue][H + uj];
            float gg = gbuf1[ue][2 * H + uj];
            float go = gbuf1[ue][3 * H + uj];
            c1 = sigf(gf) * c1 + sigf(gi) * tanhf_(gg);
            h1s[ue][uj] = sigf(go) * tanhf_(c1);
        }
        __syncthreads();

        #pragma unroll
        for (int e = 0; e < E; e++) {
            const ulonglong2* h1v = (const ulonglong2*)(&h1s[e][hf * 4 * NCH]);
            const ulonglong2* h2v = (const ulonglong2*)(&h2s[e][hf * 4 * NCH]);
            unsigned long long a = 0ull, b = 0ull;
            #pragma unroll
            for (int q = 0; q < NCH; q++) {
                ulonglong2 ha = h1v[q];
                ulonglong2 hb = h2v[q];
                fma2(a, w2a[2 * q],     ha.x);
                fma2(a, w2a[2 * q + 1], ha.y);
                fma2(b, w2b[2 * q],     hb.x);
                fma2(b, w2b[2 * q + 1], hb.y);
            }
            float s = hsum2(a) + hsum2(b);
            s += __shfl_xor_sync(0xffffffffu, s, 1);
            if (hf == 0 && pr < G4) gbuf2[e][pr] = s + bias2;
        }
        __syncthreads();

        float term = 0.f;
        if (upd) {
            float gi = gbuf2[ue][uj];
            float gf = gbuf2[ue][H + uj];
            float gg = gbuf2[ue][2 * H + uj];
            float go = gbuf2[ue][3 * H + uj];
            c2 = sigf(gf) * c2 + sigf(gi) * tanhf_(gg);
            float h2 = sigf(go) * tanhf_(c2);
            h2s[ue][uj] = h2;
            term = wlin * h2;
        }
        if (urole) {
            #pragma unroll
            for (int off = 16; off; off >>= 1)
                term += __shfl_xor_sync(0xffffffffu, term, off);
            if ((t & 31) == 0) part[(t >> 5) - 6] = term;
        }
        __syncthreads();

        if (urole && r < E) {
            float o = part[2 * r] + part[2 * r + 1] + blin;
            outs_s[r] = o;
            out[(size_t)(base + r) * TP + step] = o;
        }
        __syncthreads();
    }
}

extern "C" void kernel_launch(void* const* d_in, const int* in_sizes, int n_in,
                              void* d_out, int out_size) {
    const float* x     = (const float*)d_in[0];
    const float* W_ih1 = (const float*)d_in[1];
    const float* W_hh1 = (const float*)d_in[2];
    const float* b_ih1 = (const float*)d_in[3];
    const float* b_hh1 = (const float*)d_in[4];
    const float* W_ih2 = (const float*)d_in[5];
    const float* W_hh2 = (const float*)d_in[6];
    const float* b_ih2 = (const float*)d_in[7];
    const float* b_hh2 = (const float*)d_in[8];
    const float* W_lin = (const float*)d_in[9];
    const float* b_lin = (const float*)d_in[10];

    int T  = in_sizes[0] / BSZ;      // 1024
    int TP = out_size   / BSZ;       // 1056

    sinelstm_kernel<<<BSZ / E, NTH>>>(
        x, W_ih1, W_hh1, b_ih1, b_hh1,
        W_ih2, W_hh2, b_ih2, b_hh2,
        W_lin, b_lin, (float*)d_out, T, TP);
}

// round 6
// speedup vs baseline: 1.0129x; 1.0003x over previous
#include <cuda_runtime.h>
#include <cstdint>

#define H    50
#define G4   200     // 4*H gate rows per layer
#define E    4       // batch elements per block
#define BSZ  512
#define NTH  448     // 400 pair-threads (200 rows x 2 K-halves) + update threads
#define NCH  7       // ulonglong2 (16B) chunks per K-half
#define HPAD 56      // h padded to 14 chunks * 4 floats

// ---- packed f32x2 ops ----
__device__ __forceinline__ void fma2(unsigned long long &d, unsigned long long a, unsigned long long b) {
    asm("fma.rn.f32x2 %0, %1, %2, %0;" : "+l"(d) : "l"(a), "l"(b));
}
__device__ __forceinline__ float hsum2(unsigned long long a) {
    return __uint_as_float((unsigned)(a & 0xffffffffu)) + __uint_as_float((unsigned)(a >> 32));
}
__device__ __forceinline__ unsigned long long pk2(float lo, float hi) {
    return ((unsigned long long)__float_as_uint(hi) << 32) | (unsigned long long)__float_as_uint(lo);
}
__device__ __forceinline__ float sigf(float v) {
    return __fdividef(1.0f, 1.0f + __expf(-v));
}
__device__ __forceinline__ float tanhf_(float v) {
    return 1.0f - __fdividef(2.0f, 1.0f + __expf(2.0f * v));
}

__global__ void __launch_bounds__(NTH, 1) sinelstm_kernel(
    const float* __restrict__ x,
    const float* __restrict__ W_ih1, const float* __restrict__ W_hh1,
    const float* __restrict__ b_ih1, const float* __restrict__ b_hh1,
    const float* __restrict__ W_ih2, const float* __restrict__ W_hh2,
    const float* __restrict__ b_ih2, const float* __restrict__ b_hh2,
    const float* __restrict__ W_lin, const float* __restrict__ b_lin,
    float* __restrict__ out, int T, int TP)
{
    __shared__ __align__(16) float h1s[E][HPAD];
    __shared__ __align__(16) float h2s[E][HPAD];
    __shared__ float gbuf1[E][G4];
    __shared__ float gbuf2[E][G4];
    __shared__ float part[8];
    __shared__ float outs_s[E];

    const int t    = threadIdx.x;
    const int base = blockIdx.x * E;
    const int pr   = t >> 1;        // gate row (0..223; rows >=200 are padding)
    const int hf   = t & 1;         // K-half

    // -------- register-resident weights: row pr, K-half hf --------
    unsigned long long w1p[2 * NCH], w2a[2 * NCH], w2b[2 * NCH];
    float bias1 = 0.f, bias2 = 0.f, wx1 = 0.f;
    {
        const bool row_ok = (pr < G4);
        #pragma unroll
        for (int p = 0; p < 2 * NCH; p++) {
            int k = 2 * (hf * 2 * NCH + p);
            float a0 = (row_ok && k     < H) ? W_hh1[pr * H + k]     : 0.f;
            float a1 = (row_ok && k + 1 < H) ? W_hh1[pr * H + k + 1] : 0.f;
            w1p[p] = pk2(a0, a1);
            float c0 = (row_ok && k     < H) ? W_ih2[pr * H + k]     : 0.f;
            float c1v= (row_ok && k + 1 < H) ? W_ih2[pr * H + k + 1] : 0.f;
            w2a[p] = pk2(c0, c1v);
            float d0 = (row_ok && k     < H) ? W_hh2[pr * H + k]     : 0.f;
            float d1 = (row_ok && k + 1 < H) ? W_hh2[pr * H + k + 1] : 0.f;
            w2b[p] = pk2(d0, d1);
        }
        if (row_ok) {
            bias1 = b_ih1[pr] + b_hh1[pr];
            bias2 = b_ih2[pr] + b_hh2[pr];
            wx1   = W_ih1[pr];
        }
    }

    // -------- update role: threads 192..447 (warps 6..13, full warps) --------
    const int  r   = t - 192;
    const int  ue  = (r >> 6) & 3;
    const int  uj  = r & 63;
    const bool urole = (t >= 192);
    const bool upd   = urole && (uj < H);
    float c1 = 0.f, c2 = 0.f;
    const float wlin = upd ? W_lin[uj] : 0.f;
    const float blin = b_lin[0];

    if (t < E * HPAD) { ((float*)h1s)[t] = 0.f; ((float*)h2s)[t] = 0.f; }
    __syncthreads();

    // ================= main loop: 3 barriers/step, lagged h2/out =================
    for (int step = 0; step < T; ++step) {
        // ---- R1: gates1(step) [FMA]  ||  h2/c2 update for step-1 [MUFU] ----
        unsigned long long g1acc[E];
        #pragma unroll
        for (int e = 0; e < E; e++) {
            const ulonglong2* hv = (const ulonglong2*)(&h1s[e][hf * 4 * NCH]);
            unsigned long long acc = 0ull;
            #pragma unroll
            for (int q = 0; q < NCH; q++) {
                ulonglong2 hc = hv[q];
                fma2(acc, w1p[2 * q],     hc.x);
                fma2(acc, w1p[2 * q + 1], hc.y);
            }
            g1acc[e] = acc;
        }
        if (urole) {
            float term = 0.f;
            if (step > 0 && uj < H) {
                float gi = gbuf2[ue][uj];
                float gf = gbuf2[ue][H + uj];
                float gg = gbuf2[ue][2 * H + uj];
                float go = gbuf2[ue][3 * H + uj];
                c2 = sigf(gf) * c2 + sigf(gi) * tanhf_(gg);
                float h2 = sigf(go) * tanhf_(c2);
                h2s[ue][uj] = h2;
                term = wlin * h2;
            }
            #pragma unroll
            for (int off = 16; off; off >>= 1)
                term += __shfl_xor_sync(0xffffffffu, term, off);
            if ((t & 31) == 0) part[(t >> 5) - 6] = term;
        }
        #pragma unroll
        for (int e = 0; e < E; e++) {
            float s = hsum2(g1acc[e]);
            s += __shfl_xor_sync(0xffffffffu, s, 1);      // combine K-halves
            if (hf == 0 && pr < G4) {
                float xv = __ldg(&x[(size_t)(base + e) * T + step]);
                gbuf1[e][pr] = s + bias1 + wx1 * xv;
            }
        }
        __syncthreads();   // A

        if (step > 0 && urole && r < E)
            out[(size_t)(base + r) * TP + (step - 1)] = part[2 * r] + part[2 * r + 1] + blin;

        // ---- R2: W_hh2·h2 partial [FMA, all]  ||  h1/c1 update [MUFU] ----
        unsigned long long g2acc[E];
        #pragma unroll
        for (int e = 0; e < E; e++) {
            const ulonglong2* hv = (const ulonglong2*)(&h2s[e][hf * 4 * NCH]);
            unsigned long long acc = 0ull;
            #pragma unroll
            for (int q = 0; q < NCH; q++) {
                ulonglong2 hc = hv[q];
                fma2(acc, w2b[2 * q],     hc.x);
                fma2(acc, w2b[2 * q + 1], hc.y);
            }
            g2acc[e] = acc;
        }
        if (upd) {
            float gi = gbuf1[ue][uj];
            float gf = gbuf1[ue][H + uj];
            float gg = gbuf1[ue][2 * H + uj];
            float go = gbuf1[ue][3 * H + uj];
            c1 = sigf(gf) * c1 + sigf(gi) * tanhf_(gg);
            h1s[ue][uj] = sigf(go) * tanhf_(c1);
        }
        __syncthreads();   // B

        // ---- R3: + W_ih2·h1(new) → gates2 ----
        #pragma unroll
        for (int e = 0; e < E; e++) {
            const ulonglong2* hv = (const ulonglong2*)(&h1s[e][hf * 4 * NCH]);
            unsigned long long acc = g2acc[e];
            #pragma unroll
            for (int q = 0; q < NCH; q++) {
                ulonglong2 hc = hv[q];
                fma2(acc, w2a[2 * q],     hc.x);
                fma2(acc, w2a[2 * q + 1], hc.y);
            }
            float s = hsum2(acc);
            s += __shfl_xor_sync(0xffffffffu, s, 1);
            if (hf == 0 && pr < G4) gbuf2[e][pr] = s + bias2;
        }
        __syncthreads();   // C
    }

    // ---- epilogue: h2/out for step T-1, seed predict feedback ----
    {
        float term = 0.f;
        if (upd) {
            float gi = gbuf2[ue][uj];
            float gf = gbuf2[ue][H + uj];
            float gg = gbuf2[ue][2 * H + uj];
            float go = gbuf2[ue][3 * H + uj];
            c2 = sigf(gf) * c2 + sigf(gi) * tanhf_(gg);
            float h2 = sigf(go) * tanhf_(c2);
            h2s[ue][uj] = h2;
            term = wlin * h2;
        }
        if (urole) {
            #pragma unroll
            for (int off = 16; off; off >>= 1)
                term += __shfl_xor_sync(0xffffffffu, term, off);
            if ((t & 31) == 0) part[(t >> 5) - 6] = term;
        }
        __syncthreads();
        if (urole && r < E) {
            float o = part[2 * r] + part[2 * r + 1] + blin;
            outs_s[r] = o;
            out[(size_t)(base + r) * TP + (T - 1)] = o;
        }
        __syncthreads();
    }

    // ================= predict loop: strict ordering (output feedback) =================
    for (int step = T; step < TP; ++step) {
        #pragma unroll
        for (int e = 0; e < E; e++) {
            const ulonglong2* hv = (const ulonglong2*)(&h1s[e][hf * 4 * NCH]);
            unsigned long long acc = 0ull;
            #pragma unroll
            for (int q = 0; q < NCH; q++) {
                ulonglong2 hc = hv[q];
                fma2(acc, w1p[2 * q],     hc.x);
                fma2(acc, w1p[2 * q + 1], hc.y);
            }
            float s = hsum2(acc);
            s += __shfl_xor_sync(0xffffffffu, s, 1);
            if (hf == 0 && pr < G4)
                gbuf1[e][pr] = s + bias1 + wx1 * outs_s[e];
        }
        __syncthreads();

        if (upd) {
            float gi = gbuf1[ue][uj];
            float gf = gbuf1[ue][H + uj];
            float gg = gbuf1[ue][2 * H + uj];
            float go = gbuf1[ue][3 * H + uj];
            c1 = sigf(gf) * c1 + sigf(gi) * tanhf_(gg);
            h1s[ue][uj] = sigf(go) * tanhf_(c1);
        }
        __syncthreads();

        #pragma unroll
        for (int e = 0; e < E; e++) {
            const ulonglong2* h1v = (const ulonglong2*)(&h1s[e][hf * 4 * NCH]);
            const ulonglong2* h2v = (const ulonglong2*)(&h2s[e][hf * 4 * NCH]);
            unsigned long long a = 0ull, b = 0ull;
            #pragma unroll
            for (int q = 0; q < NCH; q++) {
                ulonglong2 ha = h1v[q];
                ulonglong2 hb = h2v[q];
                fma2(a, w2a[2 * q],     ha.x);
                fma2(a, w2a[2 * q + 1], ha.y);
                fma2(b, w2b[2 * q],     hb.x);
                fma2(b, w2b[2 * q + 1], hb.y);
            }
            float s = hsum2(a) + hsum2(b);
            s += __shfl_xor_sync(0xffffffffu, s, 1);
            if (hf == 0 && pr < G4) gbuf2[e][pr] = s + bias2;
        }
        __syncthreads();

        float term = 0.f;
        if (upd) {
            float gi = gbuf2[ue][uj];
            float gf = gbuf2[ue][H + uj];
            float gg = gbuf2[ue][2 * H + uj];
            float go = gbuf2[ue][3 * H + uj];
            c2 = sigf(gf) * c2 + sigf(gi) * tanhf_(gg);
            float h2 = sigf(go) * tanhf_(c2);
            h2s[ue][uj] = h2;
            term = wlin * h2;
        }
        if (urole) {
            #pragma unroll
            for (int off = 16; off; off >>= 1)
                term += __shfl_xor_sync(0xffffffffu, term, off);
            if ((t & 31) == 0) part[(t >> 5) - 6] = term;
        }
        __syncthreads();

        if (urole && r < E) {
            float o = part[2 * r] + part[2 * r + 1] + blin;
            outs_s[r] = o;
            out[(size_t)(base + r) * TP + step] = o;
        }
        __syncthreads();
    }
}

extern "C" void kernel_launch(void* const* d_in, const int* in_sizes, int n_in,
                              void* d_out, int out_size) {
    const float* x     = (const float*)d_in[0];
    const float* W_ih1 = (const float*)d_in[1];
    const float* W_hh1 = (const float*)d_in[2];
    const float* b_ih1 = (const float*)d_in[3];
    const float* b_hh1 = (const float*)d_in[4];
    const float* W_ih2 = (const float*)d_in[5];
    const float* W_hh2 = (const float*)d_in[6];
    const float* b_ih2 = (const float*)d_in[7];
    const float* b_hh2 = (const float*)d_in[8];
    const float* W_lin = (const float*)d_in[9];
    const float* b_lin = (const float*)d_in[10];

    int T  = in_sizes[0] / BSZ;      // 1024
    int TP = out_size   / BSZ;       // 1056

    sinelstm_kernel<<<BSZ / E, NTH>>>(
        x, W_ih1, W_hh1, b_ih1, b_hh1,
        W_ih2, W_hh2, b_ih2, b_hh2,
        W_lin, b_lin, (float*)d_out, T, TP);
}